// round 11
// baseline (speedup 1.0000x reference)
#include <cuda_runtime.h>
#include <cstdint>

// Problem constants (fixed by the dataset)
#define BB 4096
#define SS 50
#define DD 768
#define UU 768
#define QQ 200
#define QP 256   // Q padded to 256 so all GEMM dims divide evenly

// Scratch (device globals: allocation-free per harness rules)
__device__ float g_W1p[QP * UU];   // W1 zero-padded to [256, 768]
__device__ float g_b1p[QP];        // b1 zero-padded to [256]
__device__ float g_W2p[DD * QP];   // W2 zero-padded to [768, 256]
__device__ float g_qp[BB * QP];    // relu(ue @ W1p^T + b1p), stride 256
__device__ float g_w[BB * DD];     // tanh(q @ W2p^T + b2)

// ---------------------------------------------------------------------------
// Pad W1 [200,768]->[256,768], b1 [200]->[256], W2 [768,200]->[768,256]
// ---------------------------------------------------------------------------
__global__ void pad_weights(const float* __restrict__ W1, const float* __restrict__ b1,
                            const float* __restrict__ W2,
                            float* __restrict__ W1p, float* __restrict__ b1p,
                            float* __restrict__ W2p)
{
    int i = blockIdx.x * blockDim.x + threadIdx.x;
    if (i < QP * UU) {
        W1p[i] = (i < QQ * UU) ? W1[i] : 0.f;
        int cidx = i & (QP - 1);
        W2p[i] = (cidx < QQ) ? W2[(i >> 8) * QQ + cidx] : 0.f;
    }
    if (i < QP) b1p[i] = (i < QQ) ? b1[i] : 0.f;
}

// ---------------------------------------------------------------------------
// GEMM (R4 config — best measured): C[m][n] = act( A[m,:]·B[n,:] + bias[n] )
// BM=32, BN=64, BK=16, 128 threads, 4x4 microtile, double-buffered smem,
// one __syncthreads per K-iter. Grids 512 / 1536.
// ACT: 0 = relu, 1 = tanh
// ---------------------------------------------------------------------------
#define GBM 32
#define GBN 64
#define GBK 16

template <int ACT>
__global__ void __launch_bounds__(128, 8)
gemm_db(const float* __restrict__ A, const float* __restrict__ B,
        const float* __restrict__ bias, float* __restrict__ C,
        int M, int N, int K)
{
    __shared__ float As[2][GBK][GBM];
    __shared__ float Bs[2][GBK][GBN];

    const int m0 = blockIdx.x * GBM;
    const int n0 = blockIdx.y * GBN;
    const int t  = threadIdx.x;
    const int tx = t & 15;    // N dir: 16 * TN=4 = 64
    const int ty = t >> 4;    // M dir:  8 * TM=4 = 32

    const int ml = t >> 2;          // 0..31
    const int kq = (t & 3) * 4;     // 0,4,8,12

    const float* aptr  = A + (size_t)(m0 + ml) * K + kq;
    const float* bptr0 = B + (size_t)(n0 + ml) * K + kq;
    const float* bptr1 = B + (size_t)(n0 + ml + 32) * K + kq;

    float acc[4][4] = {};

    float4 ar  = *reinterpret_cast<const float4*>(aptr);
    float4 br0 = *reinterpret_cast<const float4*>(bptr0);
    float4 br1 = *reinterpret_cast<const float4*>(bptr1);
    As[0][kq + 0][ml] = ar.x;  As[0][kq + 1][ml] = ar.y;
    As[0][kq + 2][ml] = ar.z;  As[0][kq + 3][ml] = ar.w;
    Bs[0][kq + 0][ml] = br0.x; Bs[0][kq + 1][ml] = br0.y;
    Bs[0][kq + 2][ml] = br0.z; Bs[0][kq + 3][ml] = br0.w;
    Bs[0][kq + 0][ml + 32] = br1.x; Bs[0][kq + 1][ml + 32] = br1.y;
    Bs[0][kq + 2][ml + 32] = br1.z; Bs[0][kq + 3][ml + 32] = br1.w;
    __syncthreads();

    const int kIters = K / GBK;
#pragma unroll 1
    for (int it = 0; it < kIters; it++) {
        const int cur = it & 1;
        if (it + 1 < kIters) {
            const int off = (it + 1) * GBK;
            ar  = *reinterpret_cast<const float4*>(aptr  + off);
            br0 = *reinterpret_cast<const float4*>(bptr0 + off);
            br1 = *reinterpret_cast<const float4*>(bptr1 + off);
        }
#pragma unroll
        for (int k = 0; k < GBK; k++) {
            float4 a = *reinterpret_cast<const float4*>(&As[cur][k][ty * 4]);
            float4 b = *reinterpret_cast<const float4*>(&Bs[cur][k][tx * 4]);
            acc[0][0] += a.x * b.x; acc[0][1] += a.x * b.y;
            acc[0][2] += a.x * b.z; acc[0][3] += a.x * b.w;
            acc[1][0] += a.y * b.x; acc[1][1] += a.y * b.y;
            acc[1][2] += a.y * b.z; acc[1][3] += a.y * b.w;
            acc[2][0] += a.z * b.x; acc[2][1] += a.z * b.y;
            acc[2][2] += a.z * b.z; acc[2][3] += a.z * b.w;
            acc[3][0] += a.w * b.x; acc[3][1] += a.w * b.y;
            acc[3][2] += a.w * b.z; acc[3][3] += a.w * b.w;
        }
        if (it + 1 < kIters) {
            const int nxt = cur ^ 1;
            As[nxt][kq + 0][ml] = ar.x;  As[nxt][kq + 1][ml] = ar.y;
            As[nxt][kq + 2][ml] = ar.z;  As[nxt][kq + 3][ml] = ar.w;
            Bs[nxt][kq + 0][ml] = br0.x; Bs[nxt][kq + 1][ml] = br0.y;
            Bs[nxt][kq + 2][ml] = br0.z; Bs[nxt][kq + 3][ml] = br0.w;
            Bs[nxt][kq + 0][ml + 32] = br1.x; Bs[nxt][kq + 1][ml + 32] = br1.y;
            Bs[nxt][kq + 2][ml + 32] = br1.z; Bs[nxt][kq + 3][ml + 32] = br1.w;
        }
        __syncthreads();
    }

#pragma unroll
    for (int i = 0; i < 4; i++) {
        int m = m0 + ty * 4 + i;
#pragma unroll
        for (int j = 0; j < 4; j++) {
            int n = n0 + tx * 4 + j;
            float v = acc[i][j] + bias[n];
            v = (ACT == 0) ? fmaxf(v, 0.f) : tanhf(v);
            C[(size_t)m * N + n] = v;
        }
    }
}

// ---------------------------------------------------------------------------
// Attention kernel v5 ("quarter-cache"): one CTA (256 thr) per batch row.
// Rows 0..15 cached in smem (48 KB -> 4 CTAs/SM, 50% occ); rows 16..49
// streamed for the dot (lines land in L2; concurrent set ~60MB << 126MB L2)
// and re-read from L2 in phase 3b. HBM traffic unchanged (c once, out once).
// R9 measured: 2 CTAs/SM lifted DRAM 67->72%; this doubles concurrency again.
//
// SMEM: [0,256)        scores/attn (50 floats, padded)
//       [256,49408)    c rows 0..15 (16*768 floats = 48 KB)
// ---------------------------------------------------------------------------
#define RCACHE 16   // rows cached in smem
#define ATTN_SMEM_BYTES (256 + RCACHE * DD * 4)

__global__ void __launch_bounds__(256, 4)
attn_kernel(const float* __restrict__ c, const float* __restrict__ w,
            float* __restrict__ out)
{
    extern __shared__ __align__(16) unsigned char smem_raw[];
    float* attn_s = reinterpret_cast<float*>(smem_raw);
    float* c_s    = reinterpret_cast<float*>(smem_raw + 256);

    const int tid  = threadIdx.x;
    const int wi   = tid >> 5;      // 0..7
    const int lane = tid & 31;
    const int b    = blockIdx.x;

    // w row slice in registers (lane-invariant across rows)
    const float4* w4 = reinterpret_cast<const float4*>(w + (size_t)b * DD);
    float4 wr[6];
#pragma unroll
    for (int i = 0; i < 6; i++) wr[i] = __ldg(&w4[lane + i * 32]);

    const float4* c4g = reinterpret_cast<const float4*>(c + (size_t)b * (SS * DD));
    float4* c4s = reinterpret_cast<float4*>(c_s);

    // Phase 1a: rows 0..RCACHE-1 — stream to smem + dot
#pragma unroll 1
    for (int s = wi; s < RCACHE; s += 8) {
        const float4* crow = c4g + s * (DD / 4);
        float4*       srow = c4s + s * (DD / 4);
        float acc = 0.f;
#pragma unroll
        for (int i = 0; i < 6; i++) {
            float4 cv = crow[lane + i * 32];
            srow[lane + i * 32] = cv;
            acc += cv.x * wr[i].x + cv.y * wr[i].y + cv.z * wr[i].z + cv.w * wr[i].w;
        }
#pragma unroll
        for (int off = 16; off > 0; off >>= 1)
            acc += __shfl_xor_sync(0xFFFFFFFFu, acc, off);
        if (lane == 0) attn_s[s] = acc;
    }

    // Phase 1b: rows RCACHE..49 — dot only; lines allocate in L2 for phase 3b
#pragma unroll 1
    for (int s = RCACHE + wi; s < SS; s += 8) {
        const float4* crow = c4g + s * (DD / 4);
        float acc = 0.f;
#pragma unroll
        for (int i = 0; i < 6; i++) {
            float4 cv = crow[lane + i * 32];
            acc += cv.x * wr[i].x + cv.y * wr[i].y + cv.z * wr[i].z + cv.w * wr[i].w;
        }
#pragma unroll
        for (int off = 16; off > 0; off >>= 1)
            acc += __shfl_xor_sync(0xFFFFFFFFu, acc, off);
        if (lane == 0) attn_s[s] = acc;
    }
    __syncthreads();

    // Phase 2: softmax over S = 50 (warp 0)
    if (tid < 32) {
        float v0 = attn_s[lane];
        float v1 = (lane + 32 < SS) ? attn_s[lane + 32] : -1e30f;
        float m = fmaxf(v0, v1);
#pragma unroll
        for (int off = 16; off > 0; off >>= 1)
            m = fmaxf(m, __shfl_xor_sync(0xFFFFFFFFu, m, off));
        float e0 = __expf(v0 - m);
        float e1 = (lane + 32 < SS) ? __expf(v1 - m) : 0.f;
        float sum = e0 + e1;
#pragma unroll
        for (int off = 16; off > 0; off >>= 1)
            sum += __shfl_xor_sync(0xFFFFFFFFu, sum, off);
        float inv = 1.f / sum;
        attn_s[lane] = e0 * inv;
        if (lane + 32 < SS) attn_s[lane + 32] = e1 * inv;
    }
    __syncthreads();

    // Phase 3a: cached rows from smem
    float4* o4 = reinterpret_cast<float4*>(out) + (size_t)b * (SS * DD / 4);
#pragma unroll 4
    for (int i = tid; i < RCACHE * (DD / 4); i += 256) {
        int s = i / (DD / 4);
        float a = attn_s[s];
        float4 v = c4s[i];
        v.x *= a; v.y *= a; v.z *= a; v.w *= a;
        o4[i] = v;
    }
    // Phase 3b: remaining rows re-read (L2 hit), multiply, store
    const int base = RCACHE * (DD / 4);
#pragma unroll 4
    for (int i = tid; i < (SS - RCACHE) * (DD / 4); i += 256) {
        int s = RCACHE + i / (DD / 4);
        float a = attn_s[s];
        float4 v = c4g[base + i];
        v.x *= a; v.y *= a; v.z *= a; v.w *= a;
        o4[base + i] = v;
    }
}

// ---------------------------------------------------------------------------
extern "C" void kernel_launch(void* const* d_in, const int* in_sizes, int n_in,
                              void* d_out, int out_size)
{
    const float* c   = (const float*)d_in[0];   // [B,S,D]
    const float* ue  = (const float*)d_in[1];   // [B,U]
    const float* W1  = (const float*)d_in[2];   // [Q,U]
    const float* b1  = (const float*)d_in[3];   // [Q]
    const float* W2  = (const float*)d_in[4];   // [D,Q]
    const float* b2  = (const float*)d_in[5];   // [D]
    float* out = (float*)d_out;

    float *W1p, *b1p, *W2p, *qp, *wbuf;
    cudaGetSymbolAddress((void**)&W1p, g_W1p);
    cudaGetSymbolAddress((void**)&b1p, g_b1p);
    cudaGetSymbolAddress((void**)&W2p, g_W2p);
    cudaGetSymbolAddress((void**)&qp,  g_qp);
    cudaGetSymbolAddress((void**)&wbuf, g_w);

    cudaFuncSetAttribute(attn_kernel,
                         cudaFuncAttributeMaxDynamicSharedMemorySize,
                         ATTN_SMEM_BYTES);

    // Pad weights (tiny)
    pad_weights<<<(QP * UU + 255) / 256, 256>>>(W1, b1, W2, W1p, b1p, W2p);

    // q = relu(ue @ W1p^T + b1p)   M=4096, N=256, K=768 -> grid 128x4 = 512
    gemm_db<0><<<dim3(BB / GBM, QP / GBN), 128>>>(ue, W1p, b1p, qp, BB, QP, UU);
    // w = tanh(q @ W2p^T + b2)     M=4096, N=768, K=256 -> grid 128x12 = 1536
    gemm_db<1><<<dim3(BB / GBM, DD / GBN), 128>>>(qp, W2p, b2, wbuf, BB, DD, QP);
    // attention body: one CTA per batch row, 16 rows smem-cached
    attn_kernel<<<BB, 256, ATTN_SMEM_BYTES>>>(c, wbuf, out);
}

// round 15
// speedup vs baseline: 1.1137x; 1.1137x over previous
#include <cuda_runtime.h>
#include <cstdint>

// Problem constants (fixed by the dataset)
#define BB 4096
#define SS 50
#define DD 768
#define UU 768
#define QQ 200
#define QP 256   // Q padded to 256 so all GEMM dims divide evenly

// Scratch (device globals: allocation-free per harness rules)
__device__ float g_W1p[QP * UU];   // W1 zero-padded to [256, 768]
__device__ float g_b1p[QP];        // b1 zero-padded to [256]
__device__ float g_W2p[DD * QP];   // W2 zero-padded to [768, 256]
__device__ float g_qp[BB * QP];    // relu(ue @ W1p^T + b1p), stride 256
__device__ float g_w[BB * DD];     // tanh(q @ W2p^T + b2)

// ---------------------------------------------------------------------------
// Pad W1 [200,768]->[256,768], b1 [200]->[256], W2 [768,200]->[768,256]
// ---------------------------------------------------------------------------
__global__ void pad_weights(const float* __restrict__ W1, const float* __restrict__ b1,
                            const float* __restrict__ W2,
                            float* __restrict__ W1p, float* __restrict__ b1p,
                            float* __restrict__ W2p)
{
    int i = blockIdx.x * blockDim.x + threadIdx.x;
    if (i < QP * UU) {
        W1p[i] = (i < QQ * UU) ? W1[i] : 0.f;
        int cidx = i & (QP - 1);
        W2p[i] = (cidx < QQ) ? W2[(i >> 8) * QQ + cidx] : 0.f;
    }
    if (i < QP) b1p[i] = (i < QQ) ? b1[i] : 0.f;
}

// ---------------------------------------------------------------------------
// GEMM (R4 config — best measured): C[m][n] = act( A[m,:]·B[n,:] + bias[n] )
// BM=32, BN=64, BK=16, 128 threads, 4x4 microtile, double-buffered smem,
// one __syncthreads per K-iter. Grids 512 / 1536.
// ACT: 0 = relu, 1 = tanh
// ---------------------------------------------------------------------------
#define GBM 32
#define GBN 64
#define GBK 16

template <int ACT>
__global__ void __launch_bounds__(128, 8)
gemm_db(const float* __restrict__ A, const float* __restrict__ B,
        const float* __restrict__ bias, float* __restrict__ C,
        int M, int N, int K)
{
    __shared__ float As[2][GBK][GBM];
    __shared__ float Bs[2][GBK][GBN];

    const int m0 = blockIdx.x * GBM;
    const int n0 = blockIdx.y * GBN;
    const int t  = threadIdx.x;
    const int tx = t & 15;    // N dir: 16 * TN=4 = 64
    const int ty = t >> 4;    // M dir:  8 * TM=4 = 32

    const int ml = t >> 2;          // 0..31
    const int kq = (t & 3) * 4;     // 0,4,8,12

    const float* aptr  = A + (size_t)(m0 + ml) * K + kq;
    const float* bptr0 = B + (size_t)(n0 + ml) * K + kq;
    const float* bptr1 = B + (size_t)(n0 + ml + 32) * K + kq;

    float acc[4][4] = {};

    float4 ar  = *reinterpret_cast<const float4*>(aptr);
    float4 br0 = *reinterpret_cast<const float4*>(bptr0);
    float4 br1 = *reinterpret_cast<const float4*>(bptr1);
    As[0][kq + 0][ml] = ar.x;  As[0][kq + 1][ml] = ar.y;
    As[0][kq + 2][ml] = ar.z;  As[0][kq + 3][ml] = ar.w;
    Bs[0][kq + 0][ml] = br0.x; Bs[0][kq + 1][ml] = br0.y;
    Bs[0][kq + 2][ml] = br0.z; Bs[0][kq + 3][ml] = br0.w;
    Bs[0][kq + 0][ml + 32] = br1.x; Bs[0][kq + 1][ml + 32] = br1.y;
    Bs[0][kq + 2][ml + 32] = br1.z; Bs[0][kq + 3][ml + 32] = br1.w;
    __syncthreads();

    const int kIters = K / GBK;
#pragma unroll 1
    for (int it = 0; it < kIters; it++) {
        const int cur = it & 1;
        if (it + 1 < kIters) {
            const int off = (it + 1) * GBK;
            ar  = *reinterpret_cast<const float4*>(aptr  + off);
            br0 = *reinterpret_cast<const float4*>(bptr0 + off);
            br1 = *reinterpret_cast<const float4*>(bptr1 + off);
        }
#pragma unroll
        for (int k = 0; k < GBK; k++) {
            float4 a = *reinterpret_cast<const float4*>(&As[cur][k][ty * 4]);
            float4 b = *reinterpret_cast<const float4*>(&Bs[cur][k][tx * 4]);
            acc[0][0] += a.x * b.x; acc[0][1] += a.x * b.y;
            acc[0][2] += a.x * b.z; acc[0][3] += a.x * b.w;
            acc[1][0] += a.y * b.x; acc[1][1] += a.y * b.y;
            acc[1][2] += a.y * b.z; acc[1][3] += a.y * b.w;
            acc[2][0] += a.z * b.x; acc[2][1] += a.z * b.y;
            acc[2][2] += a.z * b.z; acc[2][3] += a.z * b.w;
            acc[3][0] += a.w * b.x; acc[3][1] += a.w * b.y;
            acc[3][2] += a.w * b.z; acc[3][3] += a.w * b.w;
        }
        if (it + 1 < kIters) {
            const int nxt = cur ^ 1;
            As[nxt][kq + 0][ml] = ar.x;  As[nxt][kq + 1][ml] = ar.y;
            As[nxt][kq + 2][ml] = ar.z;  As[nxt][kq + 3][ml] = ar.w;
            Bs[nxt][kq + 0][ml] = br0.x; Bs[nxt][kq + 1][ml] = br0.y;
            Bs[nxt][kq + 2][ml] = br0.z; Bs[nxt][kq + 3][ml] = br0.w;
            Bs[nxt][kq + 0][ml + 32] = br1.x; Bs[nxt][kq + 1][ml + 32] = br1.y;
            Bs[nxt][kq + 2][ml + 32] = br1.z; Bs[nxt][kq + 3][ml + 32] = br1.w;
        }
        __syncthreads();
    }

#pragma unroll
    for (int i = 0; i < 4; i++) {
        int m = m0 + ty * 4 + i;
#pragma unroll
        for (int j = 0; j < 4; j++) {
            int n = n0 + tx * 4 + j;
            float v = acc[i][j] + bias[n];
            v = (ACT == 0) ? fmaxf(v, 0.f) : tanhf(v);
            C[(size_t)m * N + n] = v;
        }
    }
}

// ---------------------------------------------------------------------------
// Attention kernel v6: one CTA (256 thr) per batch row, RCACHE=24 rows in
// smem (72 KB -> 3 CTAs/SM, 216.8 KB total smem), rows 24..49 via L2 path.
//
// Measured tradeoff so far:
//   R4:  50 cached, 1 CTA/SM -> 227us, DRAM 67.9%, traffic ~1.22GB (floor)
//   R9:  25 cached, 2 CTA/SM -> 213us, DRAM 72.4%, traffic ~1.22GB (floor)
//   R11: 16 cached, 4 CTA/SM -> 280us, DRAM 69.2%, traffic ~1.54GB (L2 MISS)
// Concurrency fills phase bubbles but the L2-path reuse set must stay small:
// here 444 CTAs * 26 rows * 3KB ~ 35MB << 126MB L2 (R11's ~60MB+ thrashed).
//
// SMEM: [0,256)        scores/attn (50 floats, padded)
//       [256,73984)    c rows 0..23 (24*768 floats = 72 KB)
// ---------------------------------------------------------------------------
#define RCACHE 24   // rows cached in smem
#define ATTN_SMEM_BYTES (256 + RCACHE * DD * 4)

__global__ void __launch_bounds__(256, 3)
attn_kernel(const float* __restrict__ c, const float* __restrict__ w,
            float* __restrict__ out)
{
    extern __shared__ __align__(16) unsigned char smem_raw[];
    float* attn_s = reinterpret_cast<float*>(smem_raw);
    float* c_s    = reinterpret_cast<float*>(smem_raw + 256);

    const int tid  = threadIdx.x;
    const int wi   = tid >> 5;      // 0..7
    const int lane = tid & 31;
    const int b    = blockIdx.x;

    // w row slice in registers (lane-invariant across rows)
    const float4* w4 = reinterpret_cast<const float4*>(w + (size_t)b * DD);
    float4 wr[6];
#pragma unroll
    for (int i = 0; i < 6; i++) wr[i] = __ldg(&w4[lane + i * 32]);

    const float4* c4g = reinterpret_cast<const float4*>(c + (size_t)b * (SS * DD));
    float4* c4s = reinterpret_cast<float4*>(c_s);

    // Phase 1a: rows 0..RCACHE-1 — stream to smem + dot
#pragma unroll 1
    for (int s = wi; s < RCACHE; s += 8) {
        const float4* crow = c4g + s * (DD / 4);
        float4*       srow = c4s + s * (DD / 4);
        float acc = 0.f;
#pragma unroll
        for (int i = 0; i < 6; i++) {
            float4 cv = crow[lane + i * 32];
            srow[lane + i * 32] = cv;
            acc += cv.x * wr[i].x + cv.y * wr[i].y + cv.z * wr[i].z + cv.w * wr[i].w;
        }
#pragma unroll
        for (int off = 16; off > 0; off >>= 1)
            acc += __shfl_xor_sync(0xFFFFFFFFu, acc, off);
        if (lane == 0) attn_s[s] = acc;
    }

    // Phase 1b: rows RCACHE..49 — dot only; lines allocate in L2 for phase 3b
#pragma unroll 1
    for (int s = RCACHE + wi; s < SS; s += 8) {
        const float4* crow = c4g + s * (DD / 4);
        float acc = 0.f;
#pragma unroll
        for (int i = 0; i < 6; i++) {
            float4 cv = crow[lane + i * 32];
            acc += cv.x * wr[i].x + cv.y * wr[i].y + cv.z * wr[i].z + cv.w * wr[i].w;
        }
#pragma unroll
        for (int off = 16; off > 0; off >>= 1)
            acc += __shfl_xor_sync(0xFFFFFFFFu, acc, off);
        if (lane == 0) attn_s[s] = acc;
    }
    __syncthreads();

    // Phase 2: softmax over S = 50 (warp 0)
    if (tid < 32) {
        float v0 = attn_s[lane];
        float v1 = (lane + 32 < SS) ? attn_s[lane + 32] : -1e30f;
        float m = fmaxf(v0, v1);
#pragma unroll
        for (int off = 16; off > 0; off >>= 1)
            m = fmaxf(m, __shfl_xor_sync(0xFFFFFFFFu, m, off));
        float e0 = __expf(v0 - m);
        float e1 = (lane + 32 < SS) ? __expf(v1 - m) : 0.f;
        float sum = e0 + e1;
#pragma unroll
        for (int off = 16; off > 0; off >>= 1)
            sum += __shfl_xor_sync(0xFFFFFFFFu, sum, off);
        float inv = 1.f / sum;
        attn_s[lane] = e0 * inv;
        if (lane + 32 < SS) attn_s[lane + 32] = e1 * inv;
    }
    __syncthreads();

    // Phase 3a: cached rows from smem
    float4* o4 = reinterpret_cast<float4*>(out) + (size_t)b * (SS * DD / 4);
#pragma unroll 4
    for (int i = tid; i < RCACHE * (DD / 4); i += 256) {
        int s = i / (DD / 4);
        float a = attn_s[s];
        float4 v = c4s[i];
        v.x *= a; v.y *= a; v.z *= a; v.w *= a;
        o4[i] = v;
    }
    // Phase 3b: remaining rows re-read (L2 hit), multiply, store
    const int base = RCACHE * (DD / 4);
#pragma unroll 4
    for (int i = tid; i < (SS - RCACHE) * (DD / 4); i += 256) {
        int s = RCACHE + i / (DD / 4);
        float a = attn_s[s];
        float4 v = c4g[base + i];
        v.x *= a; v.y *= a; v.z *= a; v.w *= a;
        o4[base + i] = v;
    }
}

// ---------------------------------------------------------------------------
extern "C" void kernel_launch(void* const* d_in, const int* in_sizes, int n_in,
                              void* d_out, int out_size)
{
    const float* c   = (const float*)d_in[0];   // [B,S,D]
    const float* ue  = (const float*)d_in[1];   // [B,U]
    const float* W1  = (const float*)d_in[2];   // [Q,U]
    const float* b1  = (const float*)d_in[3];   // [Q]
    const float* W2  = (const float*)d_in[4];   // [D,Q]
    const float* b2  = (const float*)d_in[5];   // [D]
    float* out = (float*)d_out;

    float *W1p, *b1p, *W2p, *qp, *wbuf;
    cudaGetSymbolAddress((void**)&W1p, g_W1p);
    cudaGetSymbolAddress((void**)&b1p, g_b1p);
    cudaGetSymbolAddress((void**)&W2p, g_W2p);
    cudaGetSymbolAddress((void**)&qp,  g_qp);
    cudaGetSymbolAddress((void**)&wbuf, g_w);

    cudaFuncSetAttribute(attn_kernel,
                         cudaFuncAttributeMaxDynamicSharedMemorySize,
                         ATTN_SMEM_BYTES);

    // Pad weights (tiny)
    pad_weights<<<(QP * UU + 255) / 256, 256>>>(W1, b1, W2, W1p, b1p, W2p);

    // q = relu(ue @ W1p^T + b1p)   M=4096, N=256, K=768 -> grid 128x4 = 512
    gemm_db<0><<<dim3(BB / GBM, QP / GBN), 128>>>(ue, W1p, b1p, qp, BB, QP, UU);
    // w = tanh(q @ W2p^T + b2)     M=4096, N=768, K=256 -> grid 128x12 = 1536
    gemm_db<1><<<dim3(BB / GBM, DD / GBN), 128>>>(qp, W2p, b2, wbuf, BB, DD, QP);
    // attention body: one CTA per batch row, 24 rows smem-cached
    attn_kernel<<<BB, 256, ATTN_SMEM_BYTES>>>(c, wbuf, out);
}

// round 17
// speedup vs baseline: 1.3493x; 1.2116x over previous
#include <cuda_runtime.h>
#include <cstdint>

// Problem constants (fixed by the dataset)
#define BB 4096
#define SS 50
#define DD 768
#define UU 768
#define QQ 200
#define QP 256   // Q padded to 256 so all GEMM dims divide evenly

// Scratch (device globals: allocation-free per harness rules)
__device__ float g_W1p[QP * UU];   // W1 zero-padded to [256, 768]
__device__ float g_b1p[QP];        // b1 zero-padded to [256]
__device__ float g_W2p[DD * QP];   // W2 zero-padded to [768, 256]
__device__ float g_qp[BB * QP];    // relu(ue @ W1p^T + b1p), stride 256
__device__ float g_w[BB * DD];     // tanh(q @ W2p^T + b2)

// ---------------------------------------------------------------------------
// Pad W1 [200,768]->[256,768], b1 [200]->[256], W2 [768,200]->[768,256]
// ---------------------------------------------------------------------------
__global__ void pad_weights(const float* __restrict__ W1, const float* __restrict__ b1,
                            const float* __restrict__ W2,
                            float* __restrict__ W1p, float* __restrict__ b1p,
                            float* __restrict__ W2p)
{
    int i = blockIdx.x * blockDim.x + threadIdx.x;
    if (i < QP * UU) {
        W1p[i] = (i < QQ * UU) ? W1[i] : 0.f;
        int cidx = i & (QP - 1);
        W2p[i] = (cidx < QQ) ? W2[(i >> 8) * QQ + cidx] : 0.f;
    }
    if (i < QP) b1p[i] = (i < QQ) ? b1[i] : 0.f;
}

// ---------------------------------------------------------------------------
// tf32 MMA helpers
// ---------------------------------------------------------------------------
__device__ __forceinline__ void mma_tf32(float* c, const uint32_t* a, const uint32_t* b)
{
    asm volatile(
        "mma.sync.aligned.m16n8k8.row.col.f32.tf32.tf32.f32 "
        "{%0,%1,%2,%3}, {%4,%5,%6,%7}, {%8,%9}, {%0,%1,%2,%3};"
        : "+f"(c[0]), "+f"(c[1]), "+f"(c[2]), "+f"(c[3])
        : "r"(a[0]), "r"(a[1]), "r"(a[2]), "r"(a[3]), "r"(b[0]), "r"(b[1]));
}

// Split fp32 into tf32 hi + tf32(lo) residual: v ~= hi + lo, |err| ~ 2^-21 |v|
__device__ __forceinline__ void split_tf32(float v, uint32_t& hi, uint32_t& lo)
{
    uint32_t h;
    asm("cvt.rna.tf32.f32 %0, %1;" : "=r"(h) : "f"(v));
    float lf = v - __uint_as_float(h);
    uint32_t l;
    asm("cvt.rna.tf32.f32 %0, %1;" : "=r"(l) : "f"(lf));
    hi = h; lo = l;
}

// ---------------------------------------------------------------------------
// tf32 tensor-core GEMM: C[m][n] = act( sum_k A[m][k]*B[n][k] + bias[n] )
// A [M,K] rm, B [N,K] rm (x @ W^T). All dims divide tile sizes (Q padded).
// CTA tile 64x64x16, 128 thr (4 warps, 2x2), warp tile 32x32.
// 3-term tf32 split (AhBh + AhBl + AlBh) for fp32-grade accuracy.
// Smem [k][m] / [k][n], stride 68 (pad), double-buffered gmem prefetch.
// ACT: 0 = relu, 1 = tanh
// ---------------------------------------------------------------------------
#define TBM 64
#define TBN 64
#define TBK 16
#define TST 68   // padded stride

template <int ACT>
__global__ void __launch_bounds__(128)
gemm_tf32(const float* __restrict__ A, const float* __restrict__ B,
          const float* __restrict__ bias, float* __restrict__ C,
          int M, int N, int K)
{
    __shared__ float As[2][TBK][TST];
    __shared__ float Bs[2][TBK][TST];

    const int m0 = blockIdx.x * TBM;
    const int n0 = blockIdx.y * TBN;
    const int t    = threadIdx.x;
    const int wid  = t >> 5;
    const int lane = t & 31;
    const int g    = lane >> 2;     // groupID 0..7
    const int tig  = lane & 3;      // threadID_in_group 0..3
    const int warp_m = wid & 1;     // 2 warps in M
    const int warp_n = wid >> 1;    // 2 warps in N
    const int mwb = warp_m * 32;    // warp m-base within tile
    const int nwb = warp_n * 32;    // warp n-base within tile

    // Tile-load mapping: thread owns row ml, k-chunks kq and kq+4 (float4s)
    const int ml = t >> 1;          // 0..63
    const int kq = (t & 1) * 8;     // 0 or 8

    const float* aptr = A + (size_t)(m0 + ml) * K + kq;
    const float* bptr = B + (size_t)(n0 + ml) * K + kq;

    float acc[2][4][4];             // [mtile][ntile][frag]
#pragma unroll
    for (int i = 0; i < 2; i++)
#pragma unroll
        for (int j = 0; j < 4; j++)
#pragma unroll
            for (int r = 0; r < 4; r++) acc[i][j][r] = 0.f;

    float4 av0, av1, bv0, bv1;

    // Prologue: tile 0 -> buf 0
    av0 = *reinterpret_cast<const float4*>(aptr);
    av1 = *reinterpret_cast<const float4*>(aptr + 4);
    bv0 = *reinterpret_cast<const float4*>(bptr);
    bv1 = *reinterpret_cast<const float4*>(bptr + 4);
    {
        const float aa[8] = {av0.x, av0.y, av0.z, av0.w, av1.x, av1.y, av1.z, av1.w};
        const float bb[8] = {bv0.x, bv0.y, bv0.z, bv0.w, bv1.x, bv1.y, bv1.z, bv1.w};
#pragma unroll
        for (int i = 0; i < 8; i++) {
            As[0][kq + i][ml] = aa[i];
            Bs[0][kq + i][ml] = bb[i];
        }
    }
    __syncthreads();

    const int kIters = K / TBK;
#pragma unroll 1
    for (int it = 0; it < kIters; it++) {
        const int cur = it & 1;
        if (it + 1 < kIters) {
            const int off = (it + 1) * TBK;
            av0 = *reinterpret_cast<const float4*>(aptr + off);
            av1 = *reinterpret_cast<const float4*>(aptr + off + 4);
            bv0 = *reinterpret_cast<const float4*>(bptr + off);
            bv1 = *reinterpret_cast<const float4*>(bptr + off + 4);
        }

        // Two k8 sub-steps per 16-wide tile
#pragma unroll
        for (int ks = 0; ks < TBK; ks += 8) {
            // Load + split A fragments (2 m-tiles x 4 regs)
            uint32_t ahi[2][4], alo[2][4];
#pragma unroll
            for (int mt = 0; mt < 2; mt++) {
                const int mb = mwb + mt * 16;
                split_tf32(As[cur][ks + tig    ][mb + g    ], ahi[mt][0], alo[mt][0]);
                split_tf32(As[cur][ks + tig    ][mb + g + 8], ahi[mt][1], alo[mt][1]);
                split_tf32(As[cur][ks + tig + 4][mb + g    ], ahi[mt][2], alo[mt][2]);
                split_tf32(As[cur][ks + tig + 4][mb + g + 8], ahi[mt][3], alo[mt][3]);
            }
            // Load + split B fragments (4 n-tiles x 2 regs)
            uint32_t bhi[4][2], blo[4][2];
#pragma unroll
            for (int nt = 0; nt < 4; nt++) {
                const int nb = nwb + nt * 8;
                split_tf32(Bs[cur][ks + tig    ][nb + g], bhi[nt][0], blo[nt][0]);
                split_tf32(Bs[cur][ks + tig + 4][nb + g], bhi[nt][1], blo[nt][1]);
            }
            // 3-term MMA
#pragma unroll
            for (int mt = 0; mt < 2; mt++)
#pragma unroll
                for (int nt = 0; nt < 4; nt++) {
                    mma_tf32(acc[mt][nt], ahi[mt], bhi[nt]);
                    mma_tf32(acc[mt][nt], ahi[mt], blo[nt]);
                    mma_tf32(acc[mt][nt], alo[mt], bhi[nt]);
                }
        }

        if (it + 1 < kIters) {
            const int nxt = cur ^ 1;
            const float aa[8] = {av0.x, av0.y, av0.z, av0.w, av1.x, av1.y, av1.z, av1.w};
            const float bb[8] = {bv0.x, bv0.y, bv0.z, bv0.w, bv1.x, bv1.y, bv1.z, bv1.w};
#pragma unroll
            for (int i = 0; i < 8; i++) {
                As[nxt][kq + i][ml] = aa[i];
                Bs[nxt][kq + i][ml] = bb[i];
            }
        }
        __syncthreads();
    }

    // Epilogue: bias + activation, float2 stores (c0,c1) and (c2,c3)
#pragma unroll
    for (int mt = 0; mt < 2; mt++) {
#pragma unroll
        for (int nt = 0; nt < 4; nt++) {
            const int n_c = n0 + nwb + nt * 8 + 2 * tig;
            const float b0 = __ldg(&bias[n_c]);
            const float b1 = __ldg(&bias[n_c + 1]);
            const int m_r = m0 + mwb + mt * 16 + g;

            float v0 = acc[mt][nt][0] + b0;
            float v1 = acc[mt][nt][1] + b1;
            float v2 = acc[mt][nt][2] + b0;
            float v3 = acc[mt][nt][3] + b1;
            if (ACT == 0) {
                v0 = fmaxf(v0, 0.f); v1 = fmaxf(v1, 0.f);
                v2 = fmaxf(v2, 0.f); v3 = fmaxf(v3, 0.f);
            } else {
                v0 = tanhf(v0); v1 = tanhf(v1);
                v2 = tanhf(v2); v3 = tanhf(v3);
            }
            *reinterpret_cast<float2*>(C + (size_t)m_r * N + n_c)       = make_float2(v0, v1);
            *reinterpret_cast<float2*>(C + (size_t)(m_r + 8) * N + n_c) = make_float2(v2, v3);
        }
    }
}

// ---------------------------------------------------------------------------
// Attention kernel (R9 config — measured optimum 213us): one CTA (256 thr)
// per batch row; rows 0..24 smem-cached (75KB -> 2 CTAs/SM), rows 25..49 via
// L2 double-read path (reuse set ~22MB << L2). c crosses HBM exactly once.
// Sweep: 50/1->227us, 25/2->213us, 24/3->237us, 16/4->280us (L2 thrash).
// ---------------------------------------------------------------------------
#define RCACHE 25
#define ATTN_SMEM_BYTES (256 + RCACHE * DD * 4)

__global__ void __launch_bounds__(256, 2)
attn_kernel(const float* __restrict__ c, const float* __restrict__ w,
            float* __restrict__ out)
{
    extern __shared__ __align__(16) unsigned char smem_raw[];
    float* attn_s = reinterpret_cast<float*>(smem_raw);
    float* c_s    = reinterpret_cast<float*>(smem_raw + 256);

    const int tid  = threadIdx.x;
    const int wi   = tid >> 5;
    const int lane = tid & 31;
    const int b    = blockIdx.x;

    const float4* w4 = reinterpret_cast<const float4*>(w + (size_t)b * DD);
    float4 wr[6];
#pragma unroll
    for (int i = 0; i < 6; i++) wr[i] = __ldg(&w4[lane + i * 32]);

    const float4* c4g = reinterpret_cast<const float4*>(c + (size_t)b * (SS * DD));
    float4* c4s = reinterpret_cast<float4*>(c_s);

    // Phase 1a: rows 0..24 — stream to smem + dot
#pragma unroll 1
    for (int s = wi; s < RCACHE; s += 8) {
        const float4* crow = c4g + s * (DD / 4);
        float4*       srow = c4s + s * (DD / 4);
        float acc = 0.f;
#pragma unroll
        for (int i = 0; i < 6; i++) {
            float4 cv = crow[lane + i * 32];
            srow[lane + i * 32] = cv;
            acc += cv.x * wr[i].x + cv.y * wr[i].y + cv.z * wr[i].z + cv.w * wr[i].w;
        }
#pragma unroll
        for (int off = 16; off > 0; off >>= 1)
            acc += __shfl_xor_sync(0xFFFFFFFFu, acc, off);
        if (lane == 0) attn_s[s] = acc;
    }

    // Phase 1b: rows 25..49 — dot only; lines stay in L2 for phase 3b
#pragma unroll 1
    for (int s = RCACHE + wi; s < SS; s += 8) {
        const float4* crow = c4g + s * (DD / 4);
        float acc = 0.f;
#pragma unroll
        for (int i = 0; i < 6; i++) {
            float4 cv = crow[lane + i * 32];
            acc += cv.x * wr[i].x + cv.y * wr[i].y + cv.z * wr[i].z + cv.w * wr[i].w;
        }
#pragma unroll
        for (int off = 16; off > 0; off >>= 1)
            acc += __shfl_xor_sync(0xFFFFFFFFu, acc, off);
        if (lane == 0) attn_s[s] = acc;
    }
    __syncthreads();

    // Phase 2: softmax over S = 50 (warp 0)
    if (tid < 32) {
        float v0 = attn_s[lane];
        float v1 = (lane + 32 < SS) ? attn_s[lane + 32] : -1e30f;
        float m = fmaxf(v0, v1);
#pragma unroll
        for (int off = 16; off > 0; off >>= 1)
            m = fmaxf(m, __shfl_xor_sync(0xFFFFFFFFu, m, off));
        float e0 = __expf(v0 - m);
        float e1 = (lane + 32 < SS) ? __expf(v1 - m) : 0.f;
        float sum = e0 + e1;
#pragma unroll
        for (int off = 16; off > 0; off >>= 1)
            sum += __shfl_xor_sync(0xFFFFFFFFu, sum, off);
        float inv = 1.f / sum;
        attn_s[lane] = e0 * inv;
        if (lane + 32 < SS) attn_s[lane + 32] = e1 * inv;
    }
    __syncthreads();

    // Phase 3a: cached rows from smem
    float4* o4 = reinterpret_cast<float4*>(out) + (size_t)b * (SS * DD / 4);
#pragma unroll 4
    for (int i = tid; i < RCACHE * (DD / 4); i += 256) {
        int s = i / (DD / 4);
        float a = attn_s[s];
        float4 v = c4s[i];
        v.x *= a; v.y *= a; v.z *= a; v.w *= a;
        o4[i] = v;
    }
    // Phase 3b: rows 25..49 re-read (L2 hit), multiply, store
    const int base = RCACHE * (DD / 4);
#pragma unroll 4
    for (int i = tid; i < (SS - RCACHE) * (DD / 4); i += 256) {
        int s = RCACHE + i / (DD / 4);
        float a = attn_s[s];
        float4 v = c4g[base + i];
        v.x *= a; v.y *= a; v.z *= a; v.w *= a;
        o4[base + i] = v;
    }
}

// ---------------------------------------------------------------------------
extern "C" void kernel_launch(void* const* d_in, const int* in_sizes, int n_in,
                              void* d_out, int out_size)
{
    const float* c   = (const float*)d_in[0];   // [B,S,D]
    const float* ue  = (const float*)d_in[1];   // [B,U]
    const float* W1  = (const float*)d_in[2];   // [Q,U]
    const float* b1  = (const float*)d_in[3];   // [Q]
    const float* W2  = (const float*)d_in[4];   // [D,Q]
    const float* b2  = (const float*)d_in[5];   // [D]
    float* out = (float*)d_out;

    float *W1p, *b1p, *W2p, *qp, *wbuf;
    cudaGetSymbolAddress((void**)&W1p, g_W1p);
    cudaGetSymbolAddress((void**)&b1p, g_b1p);
    cudaGetSymbolAddress((void**)&W2p, g_W2p);
    cudaGetSymbolAddress((void**)&qp,  g_qp);
    cudaGetSymbolAddress((void**)&wbuf, g_w);

    cudaFuncSetAttribute(attn_kernel,
                         cudaFuncAttributeMaxDynamicSharedMemorySize,
                         ATTN_SMEM_BYTES);

    // Pad weights (tiny)
    pad_weights<<<(QP * UU + 255) / 256, 256>>>(W1, b1, W2, W1p, b1p, W2p);

    // q = relu(ue @ W1p^T + b1p)   M=4096, N=256, K=768 -> grid 64x4 = 256
    gemm_tf32<0><<<dim3(BB / TBM, QP / TBN), 128>>>(ue, W1p, b1p, qp, BB, QP, UU);
    // w = tanh(q @ W2p^T + b2)     M=4096, N=768, K=256 -> grid 64x12 = 768
    gemm_tf32<1><<<dim3(BB / TBM, DD / TBN), 128>>>(qp, W2p, b2, wbuf, BB, DD, QP);
    // attention body: one CTA per batch row, 25 rows smem-cached (R9 optimum)
    attn_kernel<<<BB, 256, ATTN_SMEM_BYTES>>>(c, wbuf, out);
}